// round 17
// baseline (speedup 1.0000x reference)
#include <cuda_runtime.h>
#include <cuda_fp16.h>
#include <mma.h>
#include <cstdint>

using namespace nvcuda;

#define BB 64
#define SS 512
#define II 1024
#define HH 1024
#define GG 4096            // 4*H
#define KW 2048            // I + H
#define NCTA 128
#define SPLIT_SC 2048.0f
#define INV_SC  (1.0f/2048.0f)

// ---------------- static device scratch ----------------
__device__ __half g_x_hi[(size_t)BB * SS * II];
__device__ __half g_x_lo[(size_t)BB * SS * II];
__device__ __half g_w_hi[(size_t)GG * KW];
__device__ __half g_w_lo[(size_t)GG * KW];
__device__ __half g_h_hi[2][BB * HH];
__device__ __half g_h_lo[2][BB * HH];
__device__ float  g_ring[2][NCTA * 2048];        // per-CTA xw ring [b][32 gates]
__device__ unsigned g_chk[8 * 32];               // per-chunk counters, 128B apart

// ---------------- fast activations --------------------------------------
__device__ __forceinline__ float fsigmoid(float x) {
    return __fdividef(1.f, 1.f + __expf(-x));
}
__device__ __forceinline__ float ftanh(float x) {
    return 1.f - __fdividef(2.f, __expf(2.f * x) + 1.f);
}

// ---------------- pre-pass: fp16x2 split of x and W, reset state ---------
__global__ void split_init_kernel(const float* __restrict__ x,
                                  const float* __restrict__ W) {
    size_t tid = (size_t)blockIdx.x * blockDim.x + threadIdx.x;
    size_t stride = (size_t)gridDim.x * blockDim.x;
    const size_t nx = (size_t)BB * SS * II;
    const size_t nw = (size_t)GG * KW;
    for (size_t i = tid; i < nx; i += stride) {
        float v = x[i];
        __half h = __float2half_rn(v);
        g_x_hi[i] = h;
        g_x_lo[i] = __float2half_rn((v - __half2float(h)) * SPLIT_SC);
    }
    for (size_t i = tid; i < nw; i += stride) {
        float v = W[i];
        __half h = __float2half_rn(v);
        g_w_hi[i] = h;
        g_w_lo[i] = __float2half_rn((v - __half2float(h)) * SPLIT_SC);
    }
    const __half z = __float2half_rn(0.f);
    for (size_t i = tid; i < (size_t)BB * HH; i += stride) {
        g_h_hi[0][i] = z;
        g_h_lo[0][i] = z;
    }
    for (size_t i = tid; i < 8 * 32; i += stride) g_chk[i] = 0u;
}

// ---------------- fine-grained chunk wait (lane-0 poll, padded counters) ---
__device__ __forceinline__ void wait_chunk(int c, unsigned target) {
    if ((threadIdx.x & 31) == 0) {
        const unsigned* p = &g_chk[c * 32];
        unsigned v;
        do {
            asm volatile("ld.acquire.gpu.u32 %0, [%1];" : "=r"(v) : "l"(p) : "memory");
            if (v >= target) break;
            __nanosleep(20);
        } while (true);
    }
    __syncwarp();
}

// ---------------- Fused persistent LSTM -----------------------------------
// CTA owns 8 h-units (32 gate rows). Wh slice persistent in SMEM.
// Per step: recurrent GEMM (R16-proven k-split structure) -> gates -> publish
// -> xw GEMM for step t+1 (fills the inter-CTA wait bubble; no phase A kernel).
//
// SMEM byte layout:
//   [0, 66048)        whs_hi [32][1032]
//   [66048, 132096)   whs_lo [32][1032]
//   [132096, 201728)  stage region (69,632 B):
//        recurrent view: hb_hi0/hb_hi1/hb_lo0/hb_lo1, each [64][136] halves
//        xw view: 2 stages x { hi [96][72], lo [96][72] } halves (55,296 B)
//        red overlay: 8 x [32][36] f32 (36,864 B)
//   [201728, 210944)  pres [64][36] f32
//   [210944, 212992)  cs [512] f32
//   [212992, 213120)  sbias [32] f32
__global__ void __launch_bounds__(256, 1) lstm_fused_kernel(
    const float* __restrict__ bias, float* __restrict__ out)
{
    extern __shared__ char smraw[];
    half* whs_hi = (half*)smraw;
    half* whs_lo = whs_hi + 32 * 1032;
    char* stg    = smraw + 132096;
    half* hb_hi0 = (half*)stg;
    half* hb_hi1 = hb_hi0 + 64 * 136;
    half* hb_lo0 = hb_hi1 + 64 * 136;
    half* hb_lo1 = hb_lo0 + 64 * 136;
    float* red   = (float*)stg;                  // overlay
    half* xstg   = (half*)stg;                   // xw stages overlay
    float* pres  = (float*)(smraw + 201728);
    float* cs    = (float*)(smraw + 210944);
    float* sbias = (float*)(smraw + 212992);
    half* hb_hi[2] = { hb_hi0, hb_hi1 };
    half* hb_lo[2] = { hb_lo0, hb_lo1 };

    const int tid = threadIdx.x;
    const int w = tid >> 5;
    const int j0 = blockIdx.x * 8;
    const int my_chunk = j0 >> 7;
    const int mi = w & 1;          // recurrent: batch half
    const int ki = w >> 1;         // recurrent: k16-iter subset {ki, ki+4}

    // persistent Wh slice: row n -> gate g = (n/8)*1024 + j0 + (n%8), k-offset +II
    for (int i = tid; i < 4096; i += 256) {
        int n = i >> 7, q = i & 127;
        int g = ((n >> 3) << 10) + j0 + (n & 7);
        size_t src = (size_t)g * KW + II + q * 8;
        *(uint4*)&whs_hi[n * 1032 + q * 8] = *(const uint4*)&g_w_hi[src];
        *(uint4*)&whs_lo[n * 1032 + q * 8] = *(const uint4*)&g_w_lo[src];
    }
    for (int i = tid; i < 512; i += 256) cs[i] = 0.f;
    if (tid < 32) {
        int n = tid;
        sbias[n] = bias[((n >> 3) << 10) + j0 + (n & 7)];
    }
    __syncthreads();

    // ---- xw GEMM: xw[s] for this CTA's 32 gate rows -> g_ring[slot] -------
    // stage: rows 0-63 = x[b][s][k-chunk], rows 64-95 = Wx slice rows, k=64.
    auto xw_gemm = [&](int slot, int s) {
        auto issue = [&](int st, int k0) {
            uint32_t base = (uint32_t)__cvta_generic_to_shared(xstg + st * 13824);
            #pragma unroll
            for (int u = 0; u < 3; u++) {
                int g = tid + u * 256;           // 0..767
                int r = g >> 3, q8 = g & 7;
                uint32_t d = base + (uint32_t)(r * 72 + q8 * 8) * 2;
                const __half *sh, *sl;
                if (r < 64) {
                    size_t si = ((size_t)r * SS + s) * II + k0 + q8 * 8;
                    sh = &g_x_hi[si]; sl = &g_x_lo[si];
                } else {
                    int rr = r - 64;
                    int gw = ((rr >> 3) << 10) + j0 + (rr & 7);
                    size_t si = (size_t)gw * KW + k0 + q8 * 8;
                    sh = &g_w_hi[si]; sl = &g_w_lo[si];
                }
                asm volatile("cp.async.cg.shared.global [%0], [%1], 16;" :: "r"(d), "l"(sh));
                asm volatile("cp.async.cg.shared.global [%0], [%1], 16;" :: "r"(d + 6912 * 2), "l"(sl));
            }
            asm volatile("cp.async.commit_group;");
        };
        const int xm = (w & 3) * 16;    // batch tile row
        const int xn = (w >> 2) * 16;   // gate tile col (0 or 16)
        wmma::fragment<wmma::accumulator, 16, 16, 16, float> a1, a2;
        wmma::fill_fragment(a1, 0.f);
        wmma::fill_fragment(a2, 0.f);
        issue(0, 0);
        for (int ch = 0; ch < 16; ch++) {
            asm volatile("cp.async.wait_group 0;");
            __syncthreads();
            if (ch < 15) issue((ch + 1) & 1, (ch + 1) * 64);
            half* st  = xstg + (ch & 1) * 13824;
            half* stl = st + 6912;
            #pragma unroll
            for (int kc = 0; kc < 64; kc += 16) {
                wmma::fragment<wmma::matrix_a, 16, 16, 16, half, wmma::row_major> xh, xl;
                wmma::fragment<wmma::matrix_b, 16, 16, 16, half, wmma::col_major> wh_, wl_;
                wmma::load_matrix_sync(xh,  &st[xm * 72 + kc], 72);
                wmma::load_matrix_sync(xl,  &stl[xm * 72 + kc], 72);
                wmma::load_matrix_sync(wh_, &st[(64 + xn) * 72 + kc], 72);
                wmma::load_matrix_sync(wl_, &stl[(64 + xn) * 72 + kc], 72);
                wmma::mma_sync(a1, xh, wh_, a1);
                wmma::mma_sync(a2, xh, wl_, a2);
                wmma::mma_sync(a2, xl, wh_, a2);
            }
        }
        __syncthreads();   // stage region free before next recurrent use
        #pragma unroll
        for (int e = 0; e < a1.num_elements; e++) a1.x[e] += a2.x[e] * INV_SC;
        float* dst = &g_ring[slot][blockIdx.x * 2048 + xm * 32 + xn];
        wmma::store_matrix_sync(dst, a1, 32, wmma::mem_row_major);
    };

    xw_gemm(0, 0);   // prime xw[0]

    for (int t = 0; t < SS; t++) {
        const half* hbh = g_h_hi[t & 1];
        const half* hbl = g_h_lo[t & 1];
        const unsigned tgt = (unsigned)t * 16u;

        // cp.async stage one FULL 128-chunk of h (hi+lo, 16KB each)
        #define ISSUE_CHUNK(BUF, K0) { \
            uint32_t dhi = (uint32_t)__cvta_generic_to_shared(hb_hi[BUF]); \
            uint32_t dlo = (uint32_t)__cvta_generic_to_shared(hb_lo[BUF]); \
            _Pragma("unroll") \
            for (int u = 0; u < 4; u++) { \
                int idx = tid + u * 256; \
                int b = idx >> 4, q = idx & 15; \
                uint32_t doff = (uint32_t)(b * 136 + q * 8) * 2; \
                const __half* sh = &hbh[b * HH + (K0) + q * 8]; \
                const __half* sl = &hbl[b * HH + (K0) + q * 8]; \
                asm volatile("cp.async.cg.shared.global [%0], [%1], 16;" :: "r"(dhi + doff), "l"(sh)); \
                asm volatile("cp.async.cg.shared.global [%0], [%1], 16;" :: "r"(dlo + doff), "l"(sl)); \
            } \
            asm volatile("cp.async.commit_group;"); }

        wmma::fragment<wmma::accumulator, 16, 16, 16, float> acc1[2][2], acc2[2][2];
        #pragma unroll
        for (int i = 0; i < 2; i++)
            #pragma unroll
            for (int j = 0; j < 2; j++) {
                wmma::fill_fragment(acc1[i][j], 0.f);
                wmma::fill_fragment(acc2[i][j], 0.f);
            }

        if (t > 0) wait_chunk(0, tgt);
        ISSUE_CHUNK(0, 0);

        for (int c = 0; c < 8; c++) {
            asm volatile("cp.async.wait_group 0;");
            __syncthreads();
            if (c < 7) {
                if (t > 0) wait_chunk(c + 1, tgt);
                ISSUE_CHUNK((c + 1) & 1, (c + 1) * 128);
            }
            const int buf = c & 1;
            const half* Hhi = hb_hi[buf];
            const half* Hlo = hb_lo[buf];
            #pragma unroll
            for (int qq = 0; qq < 2; qq++) {
                const int kc = (ki + qq * 4) * 16;
                const int kw = c * 128 + kc;
                wmma::fragment<wmma::matrix_a, 16, 16, 16, half, wmma::row_major> ahi[2], alo[2];
                wmma::fragment<wmma::matrix_b, 16, 16, 16, half, wmma::col_major> bhi[2], blo[2];
                #pragma unroll
                for (int i = 0; i < 2; i++) {
                    wmma::load_matrix_sync(ahi[i], &Hhi[(mi * 32 + i * 16) * 136 + kc], 136);
                    wmma::load_matrix_sync(alo[i], &Hlo[(mi * 32 + i * 16) * 136 + kc], 136);
                }
                #pragma unroll
                for (int j = 0; j < 2; j++) {
                    wmma::load_matrix_sync(bhi[j], &whs_hi[(j * 16) * 1032 + kw], 1032);
                    wmma::load_matrix_sync(blo[j], &whs_lo[(j * 16) * 1032 + kw], 1032);
                }
                #pragma unroll
                for (int i = 0; i < 2; i++)
                    #pragma unroll
                    for (int j = 0; j < 2; j++) {
                        wmma::mma_sync(acc1[i][j], ahi[i], bhi[j], acc1[i][j]);
                        wmma::mma_sync(acc2[i][j], ahi[i], blo[j], acc2[i][j]);
                        wmma::mma_sync(acc2[i][j], alo[i], bhi[j], acc2[i][j]);
                    }
            }
        }
        #undef ISSUE_CHUNK

        __syncthreads();   // MMA reads done -> red overlay safe

        #pragma unroll
        for (int i = 0; i < 2; i++)
            #pragma unroll
            for (int j = 0; j < 2; j++) {
                #pragma unroll
                for (int e = 0; e < acc1[i][j].num_elements; e++)
                    acc1[i][j].x[e] += acc2[i][j].x[e] * INV_SC;
                wmma::store_matrix_sync(&red[w * 1152 + (i * 16) * 36 + j * 16],
                                        acc1[i][j], 36, wmma::mem_row_major);
            }
        __syncthreads();

        // 4-way k-reduction
        #pragma unroll
        for (int u = 0; u < 8; u++) {
            int oidx = tid + u * 256;
            int b = oidx >> 5, n = oidx & 31;
            int bmi = b >> 5, r = b & 31;
            float s = red[(0 * 2 + bmi) * 1152 + r * 36 + n]
                    + red[(1 * 2 + bmi) * 1152 + r * 36 + n]
                    + red[(2 * 2 + bmi) * 1152 + r * 36 + n]
                    + red[(3 * 2 + bmi) * 1152 + r * 36 + n];
            pres[b * 36 + n] = s;
        }
        __syncthreads();

        // gates + state update + outputs (xw from private ring, bias from smem)
        half* hwh = g_h_hi[(t + 1) & 1];
        half* hwl = g_h_lo[(t + 1) & 1];
        const float* ringr = &g_ring[t & 1][blockIdx.x * 2048];
        #pragma unroll
        for (int u = 0; u < 2; u++) {
            int i = tid + u * 256;
            int b = i >> 3, jj = i & 7;
            float pc = pres[b * 36 + jj]      + ringr[b * 32 + jj]      + sbias[jj];
            float pf = pres[b * 36 + 8 + jj]  + ringr[b * 32 + 8 + jj]  + sbias[8 + jj];
            float pu = pres[b * 36 + 16 + jj] + ringr[b * 32 + 16 + jj] + sbias[16 + jj];
            float po = pres[b * 36 + 24 + jj] + ringr[b * 32 + 24 + jj] + sbias[24 + jj];
            float cand = ftanh(pc);
            float f = fsigmoid(pf);
            float uu = fsigmoid(pu);
            float o = fsigmoid(po);
            float cn = uu * cand + f * cs[i];
            cs[i] = cn;
            float hn = o * ftanh(cn);
            __half hh = __float2half_rn(hn);
            hwh[b * HH + j0 + jj] = hh;
            hwl[b * HH + j0 + jj] = __float2half_rn((hn - __half2float(hh)) * SPLIT_SC);
            __stcs(&out[((size_t)b * SS + t) * HH + j0 + jj], hn);
            if (t == SS - 1) {
                size_t base1 = (size_t)BB * SS * HH;
                out[base1 + (size_t)b * HH + j0 + jj] = hn;
                out[base1 + (size_t)BB * HH + (size_t)b * HH + j0 + jj] = cn;
            }
        }

        // publish h for step t, then compute xw[t+1] in the wait bubble
        if (t < SS - 1) {
            __syncthreads();
            if (tid == 0) {
                __threadfence();
                atomicAdd(&g_chk[my_chunk * 32], 1u);
            }
            xw_gemm((t + 1) & 1, t + 1);
        }
    }
}

// ---------------- launch ----------------------------------------------------
extern "C" void kernel_launch(void* const* d_in, const int* in_sizes, int n_in,
                              void* d_out, int out_size) {
    const float* x    = (const float*)d_in[0];   // [64, 512, 1024]
    const float* W    = (const float*)d_in[1];   // [4096, 2048]
    const float* bias = (const float*)d_in[2];   // [4096]
    float* out = (float*)d_out;
    (void)in_sizes; (void)n_in; (void)out_size;

    const int smemF = 213120;

    cudaFuncSetAttribute(lstm_fused_kernel,
                         cudaFuncAttributeMaxDynamicSharedMemorySize, smemF);

    split_init_kernel<<<512, 256>>>(x, W);
    lstm_fused_kernel<<<NCTA, 256, smemF>>>(bias, out);
}